// round 5
// baseline (speedup 1.0000x reference)
#include <cuda_runtime.h>
#include <cfloat>

#define NROWS   32768
#define NCTR    512
#define DIM     128
#define TOPK    10

#define BM 128
#define BN 128            // centers per chunk
#define NCHUNK (NCTR / BN) // 4
#define BK 8
#define NSTAGE (DIM / BK)  // 16
#define CTA 256

__device__ float g_c2[NCTR];
__device__ float g_x2[NROWS];

// ---------------------------------------------------------------------------
// Kernel 0: x2 and c2, correctly rounded (double accumulation). 1 warp/row.
// ---------------------------------------------------------------------------
__global__ void norms_kernel(const float* __restrict__ x,
                             const float* __restrict__ ctr) {
    int warp = (blockIdx.x * blockDim.x + threadIdx.x) >> 5;
    int lane = threadIdx.x & 31;
    const float* src;
    float* dst;
    if (warp < NROWS) {
        src = x + (size_t)warp * DIM;
        dst = &g_x2[warp];
    } else if (warp < NROWS + NCTR) {
        src = ctr + (size_t)(warp - NROWS) * DIM;
        dst = &g_c2[warp - NROWS];
    } else {
        return;
    }
    float4 v = reinterpret_cast<const float4*>(src)[lane];
    double s = (double)v.x * v.x + (double)v.y * v.y
             + (double)v.z * v.z + (double)v.w * v.w;
    #pragma unroll
    for (int o = 16; o; o >>= 1) s += __shfl_xor_sync(0xffffffffu, s, o);
    if (lane == 0) *dst = (float)s;
}

// ---------------------------------------------------------------------------
// Fused kernel: per 128-row block, loop 4 center chunks:
//   GEMM 128x128x128 (8x8 thread tile, BK=8 double-buffered)
//   -> d = sqrt_rn(max(fl(fl(x2 - fl(2*dot)) + c2), 0)) into smem dbuf
//   -> per-row top-10 merge into running sorted list (exact (val,idx) lex)
// then fused gather-write of the output. Keys never touch HBM.
//
// Invariant: dot is ONE sequential ascending-k FMA chain per element.
// smem: as 8K + bs 8K + dbuf 64K + 2x best(val,idx) 20K = 100KB, 2 CTAs/SM.
// ---------------------------------------------------------------------------
__global__ void __launch_bounds__(CTA, 2)
fused_kernel(const float* __restrict__ x,
             const float* __restrict__ ctr,
             float* __restrict__ out) {
    extern __shared__ float smem[];
    float (*as)[BK][BM]   = reinterpret_cast<float (*)[BK][BM]>(smem);            // [2][8][128]
    float (*bs)[BK][BN]   = reinterpret_cast<float (*)[BK][BN]>(smem + 2048);     // [2][8][128]
    float (*dbuf)[BN]     = reinterpret_cast<float (*)[BN]>(smem + 4096);         // [128][128]
    float* bestV[2];  int* bestI[2];
    bestV[0] = smem + 4096 + 16384;                         // [128][10]
    bestI[0] = reinterpret_cast<int*>(bestV[0] + BM * TOPK);
    bestV[1] = reinterpret_cast<float*>(bestI[0] + BM * TOPK);
    bestI[1] = reinterpret_cast<int*>(bestV[1] + BM * TOPK);

    const int tid    = threadIdx.x;
    const int rowBlk = blockIdx.x * BM;

    const int lr = tid >> 1;            // 0..127 (loader row)
    const int lq = tid & 1;             // 0..1   (loader k-quad)
    const float4* xsrc = reinterpret_cast<const float4*>(x + (size_t)(rowBlk + lr) * DIM);

    const int tx = tid & 15;
    const int ty = tid >> 4;

    const int warp = tid >> 5;
    const int lane = tid & 31;

    // init running best lists (parity 0) to +inf
    for (int i = tid; i < BM * TOPK; i += CTA) {
        bestV[0][i] = FLT_MAX;
        bestI[0][i] = 0x7fffffff;
    }

    float x2v[8];
    #pragma unroll
    for (int i = 0; i < 8; i++) x2v[i] = g_x2[rowBlk + ty * 8 + i];

    int cur = 0;

    for (int chunk = 0; chunk < NCHUNK; chunk++) {
        const int cBase = chunk * BN;
        const float4* csrc = reinterpret_cast<const float4*>(ctr + (size_t)(cBase + lr) * DIM);

        float acc[8][8];
        #pragma unroll
        for (int i = 0; i < 8; i++)
            #pragma unroll
            for (int j = 0; j < 8; j++) acc[i][j] = 0.0f;

        // stage 0
        float4 av = xsrc[lq];
        float4 bv = csrc[lq];
        __syncthreads();   // prev selection done (dbuf/best) & init done (chunk 0)
        as[0][lq * 4 + 0][lr] = av.x; as[0][lq * 4 + 1][lr] = av.y;
        as[0][lq * 4 + 2][lr] = av.z; as[0][lq * 4 + 3][lr] = av.w;
        bs[0][lq * 4 + 0][lr] = bv.x; bs[0][lq * 4 + 1][lr] = bv.y;
        bs[0][lq * 4 + 2][lr] = bv.z; bs[0][lq * 4 + 3][lr] = bv.w;
        __syncthreads();

        for (int s = 0; s < NSTAGE; s++) {
            const int buf = s & 1;
            if (s + 1 < NSTAGE) {
                av = xsrc[(s + 1) * 2 + lq];
                bv = csrc[(s + 1) * 2 + lq];
            }
            #pragma unroll
            for (int k = 0; k < BK; k++) {
                float a[8], b[8];
                *reinterpret_cast<float4*>(&a[0]) = *reinterpret_cast<const float4*>(&as[buf][k][ty * 8]);
                *reinterpret_cast<float4*>(&a[4]) = *reinterpret_cast<const float4*>(&as[buf][k][ty * 8 + 4]);
                *reinterpret_cast<float4*>(&b[0]) = *reinterpret_cast<const float4*>(&bs[buf][k][tx * 8]);
                *reinterpret_cast<float4*>(&b[4]) = *reinterpret_cast<const float4*>(&bs[buf][k][tx * 8 + 4]);
                #pragma unroll
                for (int i = 0; i < 8; i++)
                    #pragma unroll
                    for (int j = 0; j < 8; j++)
                        acc[i][j] = fmaf(a[i], b[j], acc[i][j]);
            }
            if (s + 1 < NSTAGE) {
                const int nbuf = 1 - buf;
                as[nbuf][lq * 4 + 0][lr] = av.x; as[nbuf][lq * 4 + 1][lr] = av.y;
                as[nbuf][lq * 4 + 2][lr] = av.z; as[nbuf][lq * 4 + 3][lr] = av.w;
                bs[nbuf][lq * 4 + 0][lr] = bv.x; bs[nbuf][lq * 4 + 1][lr] = bv.y;
                bs[nbuf][lq * 4 + 2][lr] = bv.z; bs[nbuf][lq * 4 + 3][lr] = bv.w;
                __syncthreads();
            }
        }

        // epilogue: exact reference rounding, into smem dbuf
        float c2v[8];
        #pragma unroll
        for (int j = 0; j < 8; j++) c2v[j] = g_c2[cBase + tx * 8 + j];

        #pragma unroll
        for (int i = 0; i < 8; i++) {
            #pragma unroll
            for (int g = 0; g < 2; g++) {
                float4 kv;
                float d2;
                d2 = __fadd_rn(__fsub_rn(x2v[i], __fmul_rn(2.0f, acc[i][g*4+0])), c2v[g*4+0]);
                kv.x = __fsqrt_rn(fmaxf(d2, 0.0f));
                d2 = __fadd_rn(__fsub_rn(x2v[i], __fmul_rn(2.0f, acc[i][g*4+1])), c2v[g*4+1]);
                kv.y = __fsqrt_rn(fmaxf(d2, 0.0f));
                d2 = __fadd_rn(__fsub_rn(x2v[i], __fmul_rn(2.0f, acc[i][g*4+2])), c2v[g*4+2]);
                kv.z = __fsqrt_rn(fmaxf(d2, 0.0f));
                d2 = __fadd_rn(__fsub_rn(x2v[i], __fmul_rn(2.0f, acc[i][g*4+3])), c2v[g*4+3]);
                kv.w = __fsqrt_rn(fmaxf(d2, 0.0f));
                *reinterpret_cast<float4*>(&dbuf[ty * 8 + i][tx * 8 + g * 4]) = kv;
            }
        }
        __syncthreads();   // dbuf complete

        // ---- selection: warp w handles rows w*16..w*16+15 ----
        const int nxt = 1 - cur;
        for (int rr = 0; rr < 16; rr++) {
            const int r = warp * 16 + rr;

            // lane's 4 candidates, sorted ascending (val, idx) via network
            float4 t = *reinterpret_cast<const float4*>(&dbuf[r][lane * 4]);
            float lv[4] = {t.x, t.y, t.z, t.w};
            int   li[4] = {cBase + lane * 4 + 0, cBase + lane * 4 + 1,
                           cBase + lane * 4 + 2, cBase + lane * 4 + 3};
            #define CSWAP(a, b) { \
                bool sw = (lv[b] < lv[a]) || (lv[b] == lv[a] && li[b] < li[a]); \
                if (sw) { float tv = lv[a]; lv[a] = lv[b]; lv[b] = tv; \
                          int ti = li[a]; li[a] = li[b]; li[b] = ti; } }
            CSWAP(0, 1) CSWAP(2, 3) CSWAP(0, 2) CSWAP(1, 3) CSWAP(1, 2)
            #undef CSWAP

            // streamed merge: pop warp-argmin of new candidates vs old list
            int pl = 0;   // per-lane pointer into lv
            int po = 0;   // warp-uniform pointer into old best
            #pragma unroll
            for (int s2 = 0; s2 < TOPK; s2++) {
                float hv = (pl < 4) ? lv[pl] : FLT_MAX;
                int   hi = (pl < 4) ? li[pl] : 0x7fffffff;
                float mv = hv; int mi = hi;
                #pragma unroll
                for (int o = 16; o; o >>= 1) {
                    float ov = __shfl_xor_sync(0xffffffffu, mv, o);
                    int   oi = __shfl_xor_sync(0xffffffffu, mi, o);
                    if (ov < mv || (ov == mv && oi < mi)) { mv = ov; mi = oi; }
                }
                float ov2 = bestV[cur][r * TOPK + po];
                int   oi2 = bestI[cur][r * TOPK + po];
                bool takeOld = (ov2 < mv) || (ov2 == mv && oi2 < mi);
                float wv; int wi;
                if (takeOld) { wv = ov2; wi = oi2; po++; }
                else { wv = mv; wi = mi; if (pl < 4 && hi == mi) pl++; }
                if (lane == 0) {
                    bestV[nxt][r * TOPK + s2] = wv;
                    bestI[nxt][r * TOPK + s2] = wi;
                }
            }
        }
        cur = 1 - cur;
        __syncthreads();   // best[nxt] complete; dbuf free for next chunk
    }

    // ---- fused gather-write: warp w rows w*16..+15 ----
    float4* out4 = reinterpret_cast<float4*>(out);
    for (int rr = 0; rr < 16; rr++) {
        const int r = warp * 16 + rr;
        const size_t outRowBase = (size_t)(rowBlk + r) * TOPK;
        #pragma unroll
        for (int s = 0; s < TOPK; s++) {
            int mi = bestI[cur][r * TOPK + s];     // broadcast smem read
            const float4* srcRow = reinterpret_cast<const float4*>(x + (size_t)mi * DIM);
            out4[(outRowBase + s) * (DIM / 4) + lane] = srcRow[lane];
        }
    }
}

// ---------------------------------------------------------------------------
extern "C" void kernel_launch(void* const* d_in, const int* in_sizes, int n_in,
                              void* d_out, int out_size) {
    const float* x;
    const float* ctr;
    if (in_sizes[0] == NCTR * DIM && n_in >= 2) {
        ctr = (const float*)d_in[0];
        x   = (const float*)d_in[1];
    } else {
        x   = (const float*)d_in[0];
        ctr = (const float*)d_in[1];
    }
    float* out = (float*)d_out;

    static const size_t SMEM_BYTES = (2048 + 2048 + 16384 + 4 * BM * TOPK) * sizeof(float); // 102400
    cudaFuncSetAttribute(fused_kernel, cudaFuncAttributeMaxDynamicSharedMemorySize, (int)SMEM_BYTES);

    int totalWarps = NROWS + NCTR;
    int normBlocks = (totalWarps * 32 + 255) / 256;
    norms_kernel<<<normBlocks, 256>>>(x, ctr);

    fused_kernel<<<NROWS / BM, CTA, SMEM_BYTES>>>(x, ctr, out);
}

// round 6
// speedup vs baseline: 2.2257x; 2.2257x over previous
#include <cuda_runtime.h>
#include <cfloat>

#define NROWS   32768
#define NCTR    512
#define DIM     128
#define TOPK    10

#define BM 128
#define BN 128
#define BK 8
#define NSTAGE (DIM / BK)     // 16
#define GCTA 256

// Scratch (static device globals: allocation-free).
__device__ float g_c2[NCTR];
__device__ float g_x2[NROWS];
__device__ float g_keys[(size_t)NROWS * NCTR];   // 64 MB distance keys

// ---------------------------------------------------------------------------
// Kernel 0: x2 and c2, correctly rounded (double accumulation). 1 warp/row.
// ---------------------------------------------------------------------------
__global__ void norms_kernel(const float* __restrict__ x,
                             const float* __restrict__ ctr) {
    int warp = (blockIdx.x * blockDim.x + threadIdx.x) >> 5;
    int lane = threadIdx.x & 31;
    const float* src;
    float* dst;
    if (warp < NROWS) {
        src = x + (size_t)warp * DIM;
        dst = &g_x2[warp];
    } else if (warp < NROWS + NCTR) {
        src = ctr + (size_t)(warp - NROWS) * DIM;
        dst = &g_c2[warp - NROWS];
    } else {
        return;
    }
    float4 v = reinterpret_cast<const float4*>(src)[lane];
    double s = (double)v.x * v.x + (double)v.y * v.y
             + (double)v.z * v.z + (double)v.w * v.w;
    #pragma unroll
    for (int o = 16; o; o >>= 1) s += __shfl_xor_sync(0xffffffffu, s, o);
    if (lane == 0) *dst = (float)s;
}

// ---------------------------------------------------------------------------
// Kernel 1: 32768x512x128 SGEMM -> distance keys. (UNCHANGED from R4 — the
// exactness invariant lives here: dot is ONE sequential ascending-k FMA
// chain per element; epilogue rounding mimics the reference bit-structure.)
// ---------------------------------------------------------------------------
__global__ void __launch_bounds__(GCTA, 2)
gemm_keys_kernel(const float* __restrict__ x,
                 const float* __restrict__ ctr) {
    __shared__ float as[2][BK][BM];
    __shared__ float bs[2][BK][BN];

    const int tid    = threadIdx.x;
    const int rowBlk = blockIdx.x * BM;
    const int ctrBlk = blockIdx.y * BN;

    const int lr = tid >> 1;          // 0..127
    const int lq = tid & 1;           // 0..1
    const float4* xsrc = reinterpret_cast<const float4*>(x   + (size_t)(rowBlk + lr) * DIM);
    const float4* csrc = reinterpret_cast<const float4*>(ctr + (size_t)(ctrBlk + lr) * DIM);

    const int tx = tid & 15;
    const int ty = tid >> 4;

    float acc[8][8];
    #pragma unroll
    for (int i = 0; i < 8; i++)
        #pragma unroll
        for (int j = 0; j < 8; j++) acc[i][j] = 0.0f;

    float4 av = xsrc[lq];
    float4 bv = csrc[lq];
    as[0][lq * 4 + 0][lr] = av.x; as[0][lq * 4 + 1][lr] = av.y;
    as[0][lq * 4 + 2][lr] = av.z; as[0][lq * 4 + 3][lr] = av.w;
    bs[0][lq * 4 + 0][lr] = bv.x; bs[0][lq * 4 + 1][lr] = bv.y;
    bs[0][lq * 4 + 2][lr] = bv.z; bs[0][lq * 4 + 3][lr] = bv.w;
    __syncthreads();

    for (int s = 0; s < NSTAGE; s++) {
        const int buf = s & 1;
        if (s + 1 < NSTAGE) {
            av = xsrc[(s + 1) * 2 + lq];
            bv = csrc[(s + 1) * 2 + lq];
        }

        #pragma unroll
        for (int k = 0; k < BK; k++) {
            float a[8], b[8];
            *reinterpret_cast<float4*>(&a[0]) = *reinterpret_cast<const float4*>(&as[buf][k][ty * 8]);
            *reinterpret_cast<float4*>(&a[4]) = *reinterpret_cast<const float4*>(&as[buf][k][ty * 8 + 4]);
            *reinterpret_cast<float4*>(&b[0]) = *reinterpret_cast<const float4*>(&bs[buf][k][tx * 8]);
            *reinterpret_cast<float4*>(&b[4]) = *reinterpret_cast<const float4*>(&bs[buf][k][tx * 8 + 4]);
            #pragma unroll
            for (int i = 0; i < 8; i++)
                #pragma unroll
                for (int j = 0; j < 8; j++)
                    acc[i][j] = fmaf(a[i], b[j], acc[i][j]);
        }

        if (s + 1 < NSTAGE) {
            const int nbuf = 1 - buf;
            as[nbuf][lq * 4 + 0][lr] = av.x; as[nbuf][lq * 4 + 1][lr] = av.y;
            as[nbuf][lq * 4 + 2][lr] = av.z; as[nbuf][lq * 4 + 3][lr] = av.w;
            bs[nbuf][lq * 4 + 0][lr] = bv.x; bs[nbuf][lq * 4 + 1][lr] = bv.y;
            bs[nbuf][lq * 4 + 2][lr] = bv.z; bs[nbuf][lq * 4 + 3][lr] = bv.w;
            __syncthreads();
        }
    }

    float x2v[8], c2v[8];
    #pragma unroll
    for (int i = 0; i < 8; i++) x2v[i] = g_x2[rowBlk + ty * 8 + i];
    #pragma unroll
    for (int j = 0; j < 8; j++) c2v[j] = g_c2[ctrBlk + tx * 8 + j];

    #pragma unroll
    for (int i = 0; i < 8; i++) {
        const size_t rowOff = (size_t)(rowBlk + ty * 8 + i) * NCTR + ctrBlk + tx * 8;
        #pragma unroll
        for (int g = 0; g < 2; g++) {
            float4 kv;
            float d2;
            d2 = __fadd_rn(__fsub_rn(x2v[i], __fmul_rn(2.0f, acc[i][g*4+0])), c2v[g*4+0]);
            kv.x = __fsqrt_rn(fmaxf(d2, 0.0f));
            d2 = __fadd_rn(__fsub_rn(x2v[i], __fmul_rn(2.0f, acc[i][g*4+1])), c2v[g*4+1]);
            kv.y = __fsqrt_rn(fmaxf(d2, 0.0f));
            d2 = __fadd_rn(__fsub_rn(x2v[i], __fmul_rn(2.0f, acc[i][g*4+2])), c2v[g*4+2]);
            kv.z = __fsqrt_rn(fmaxf(d2, 0.0f));
            d2 = __fadd_rn(__fsub_rn(x2v[i], __fmul_rn(2.0f, acc[i][g*4+3])), c2v[g*4+3]);
            kv.w = __fsqrt_rn(fmaxf(d2, 0.0f));
            *reinterpret_cast<float4*>(&g_keys[rowOff + g * 4]) = kv;
        }
    }
}

// ---------------------------------------------------------------------------
// Kernel 2: per-row top-10 selection + gather. One warp per row.
//
// u64 packed key = (float_bits(d) << 32) | idx. d >= 0 so this is
// order-isomorphic to the exact (val asc, idx asc) lex comparator.
// Argmin rounds use REDUX.SYNC.MIN (flat latency) instead of shuffle chains.
// ---------------------------------------------------------------------------
__global__ void __launch_bounds__(256)
select_kernel(const float* __restrict__ x, float* __restrict__ out) {
    const int row  = blockIdx.x * 8 + (threadIdx.x >> 5);
    const int lane = threadIdx.x & 31;

    const float4* krow = reinterpret_cast<const float4*>(g_keys + (size_t)row * NCTR);

    // per-lane sorted top-10 (u64 insertion over 16 candidates)
    unsigned long long b[TOPK];
    #pragma unroll
    for (int j = 0; j < TOPK; j++) b[j] = ~0ull;

    #pragma unroll
    for (int q = 0; q < 4; q++) {
        float4 t = krow[q * 32 + lane];
        float vv[4] = {t.x, t.y, t.z, t.w};
        #pragma unroll
        for (int j4 = 0; j4 < 4; j4++) {
            unsigned long long key =
                ((unsigned long long)__float_as_uint(vv[j4]) << 32)
                | (unsigned)(q * 128 + lane * 4 + j4);
            if (key < b[TOPK - 1]) {
                b[TOPK - 1] = key;
                #pragma unroll
                for (int j = TOPK - 1; j > 0; j--) {
                    if (b[j] < b[j - 1]) {
                        unsigned long long t2 = b[j]; b[j] = b[j - 1]; b[j - 1] = t2;
                    }
                }
            }
        }
    }

    // 10 rounds: REDUX argmin over lane heads; winner pops; fused gather.
    float4* out4 = reinterpret_cast<float4*>(out);
    const size_t outRowBase = (size_t)row * TOPK;
    #pragma unroll
    for (int s = 0; s < TOPK; s++) {
        unsigned hv = (unsigned)(b[0] >> 32);          // float bits (monotone)
        unsigned hi = (unsigned)(b[0] & 0xffffffffu);  // index
        unsigned m  = __reduce_min_sync(0xffffffffu, hv);
        unsigned ci = (hv == m) ? hi : 0xffffffffu;
        unsigned mi = __reduce_min_sync(0xffffffffu, ci);

        // gather: out[row*10+s][:] = x[mi][:]  (mi < 512, L2-resident)
        const float4* srcRow = reinterpret_cast<const float4*>(x + (size_t)mi * DIM);
        out4[(outRowBase + s) * (DIM / 4) + lane] = srcRow[lane];

        // pop on the unique owning lane (static-index shift, no spill)
        if (hv == m && hi == mi) {
            #pragma unroll
            for (int j = 0; j < TOPK - 1; j++) b[j] = b[j + 1];
            b[TOPK - 1] = ~0ull;
        }
    }
}

// ---------------------------------------------------------------------------
extern "C" void kernel_launch(void* const* d_in, const int* in_sizes, int n_in,
                              void* d_out, int out_size) {
    const float* x;
    const float* ctr;
    if (in_sizes[0] == NCTR * DIM && n_in >= 2) {
        ctr = (const float*)d_in[0];
        x   = (const float*)d_in[1];
    } else {
        x   = (const float*)d_in[0];
        ctr = (const float*)d_in[1];
    }
    float* out = (float*)d_out;

    int totalWarps = NROWS + NCTR;
    int normBlocks = (totalWarps * 32 + 255) / 256;
    norms_kernel<<<normBlocks, 256>>>(x, ctr);

    dim3 ggrid(NROWS / BM, NCTR / BN);        // 256 x 4
    gemm_keys_kernel<<<ggrid, GCTA>>>(x, ctr);

    select_kernel<<<NROWS / 8, 256>>>(x, out);
}